// round 16
// baseline (speedup 1.0000x reference)
#include <cuda_runtime.h>
#include <cuda_bf16.h>
#include <math.h>
#include <cstdint>

#define B_SZ  4096
#define DIN   256
#define NOUT  32
#define MM    128
#define NH    2
#define HOC   (NH*NOUT)
#define JIT   1e-4f
#define TRILN (MM*(MM+1)/2)
#define D2CUT 170.0f

// ---------------- scratch ----------------
__device__ float g_sf2v[NH];
__device__ float g_x2[NH*B_SZ];
__device__ float g_z2[HOC*MM];
__device__ __align__(16) __nv_bfloat16 g_xb[NH*B_SZ*DIN];
__device__ __align__(16) __nv_bfloat16 g_zb[HOC*MM*DIN];
__device__ __align__(16) __nv_bfloat16 g_kscr[1024*MM*MM];  // rare-path kuf scratch

// ---------------- helpers ----------------
__device__ __forceinline__ uint32_t smem_u32(const void* p){
  uint32_t a;
  asm("{ .reg .u64 t; cvta.to.shared.u64 t, %1; cvt.u32.u64 %0, t; }" : "=r"(a) : "l"(p));
  return a;
}
__device__ __forceinline__ void ldsm4(uint32_t addr, uint32_t* r){
  asm volatile("ldmatrix.sync.aligned.m8n8.x4.shared.b16 {%0,%1,%2,%3}, [%4];"
    : "=r"(r[0]),"=r"(r[1]),"=r"(r[2]),"=r"(r[3]) : "r"(addr));
}
__device__ __forceinline__ void mma16816(float* c, const uint32_t* a, const uint32_t* b){
  asm volatile("mma.sync.aligned.m16n8k16.row.col.f32.bf16.bf16.f32 "
    "{%0,%1,%2,%3}, {%4,%5,%6,%7}, {%8,%9}, {%0,%1,%2,%3};"
    : "+f"(c[0]),"+f"(c[1]),"+f"(c[2]),"+f"(c[3])
    : "r"(a[0]),"r"(a[1]),"r"(a[2]),"r"(a[3]), "r"(b[0]),"r"(b[1]));
}
#define CP16(dst, src) asm volatile("cp.async.cg.shared.global [%0], [%1], 16;" :: "r"(dst), "l"(src))
#define CP_COMMIT()    asm volatile("cp.async.commit_group;" ::: "memory")
#define CP_WAIT(n)     asm volatile("cp.async.wait_group %0;" :: "n"(n) : "memory")

__device__ __forceinline__ uint32_t pack_bf16x2(float lo, float hi){
  uint32_t r;
  asm("cvt.rn.satfinite.bf16x2.f32 %0, %1, %2;" : "=r"(r) : "f"(hi), "f"(lo));
  return r;
}
__device__ __forceinline__ float rbf(float sf2, float d2){
  return (d2 < D2CUT) ? sf2*__expf(-0.5f*d2) : 0.f;
}

#define SP64   144      // K=64 stage pitch bytes (128 B data + 16 B pad)
#define ZST64  18432    // one K=64 z stage: 128*144
#define KPITCH 272
#define XP     528
#define G      4

// 128x128x128 bf16 block GEMM from KPITCH tiles (rare-path NS)
__device__ __forceinline__ void mm128(uint32_t aBase, uint32_t bBase,
                                      int wr, int wc, int l15, int lh,
                                      float acc[16][4]){
  uint32_t aB0 = aBase + (wr*32 + l15)*KPITCH + lh*16;
  uint32_t bB0 = bBase + (wc*64 + l15)*KPITCH + lh*16;
  #pragma unroll
  for (int ks=0;ks<8;ks++){
    uint32_t af[2][4], bt[4], bfr[8][2];
    #pragma unroll
    for (int mt=0;mt<2;mt++) ldsm4(aB0 + ks*32 + mt*16*KPITCH, af[mt]);
    #pragma unroll
    for (int nn=0;nn<4;nn++){
      ldsm4(bB0 + ks*32 + nn*16*KPITCH, bt);
      bfr[nn*2][0]=bt[0]; bfr[nn*2][1]=bt[2];
      bfr[nn*2+1][0]=bt[1]; bfr[nn*2+1][1]=bt[3];
    }
    #pragma unroll
    for (int mt=0;mt<2;mt++)
      #pragma unroll
      for (int nf=0;nf<8;nf++)
        mma16816(acc[mt*8+nf], af[mt], bfr[nf]);
  }
}

// one K=64 chunk: A resident x (XP pitch), B z stage (SP64 pitch)
__device__ __forceinline__ void chunk64x(uint32_t aB, uint32_t bB, float acc[16][4]){
  #pragma unroll
  for (int ks=0;ks<4;ks++){
    uint32_t af[2][4], bt[4], bfr[8][2];
    #pragma unroll
    for (int mt=0;mt<2;mt++) ldsm4(aB + ks*32 + mt*16*XP, af[mt]);
    #pragma unroll
    for (int nn=0;nn<4;nn++){
      ldsm4(bB + ks*32 + nn*16*SP64, bt);
      bfr[nn*2][0]=bt[0]; bfr[nn*2][1]=bt[2];
      bfr[nn*2+1][0]=bt[1]; bfr[nn*2+1][1]=bt[3];
    }
    #pragma unroll
    for (int mt=0;mt<2;mt++)
      #pragma unroll
      for (int nf=0;nf<8;nf++)
        mma16816(acc[mt*8+nf], af[mt], bfr[nf]);
  }
}

// ---------------- prep (unchanged) ----------------
__global__ void k_prep(const float* __restrict__ x, const float* __restrict__ z,
                       const float* __restrict__ theta){
  __shared__ float sscal[256];
  __shared__ float sw[8];
  int tid = threadIdx.x;
  int lane = tid & 31, wid = tid >> 5;
  int row0 = blockIdx.x*4;
  int hblk = (row0 < NH*B_SZ) ? (row0 / B_SZ)
                              : ((row0 - NH*B_SZ) / (NOUT*MM));
  sscal[tid] = expf(-theta[hblk*(DIN+1) + 1 + tid]);
  if (blockIdx.x == 0 && tid < NH) g_sf2v[tid] = expf(theta[tid*(DIN+1)]);
  __syncthreads();

  int rloc = tid >> 6;
  int col  = (tid & 63) << 2;
  int row  = row0 + rloc;

  const float* src; __nv_bfloat16* dst;
  if (row < NH*B_SZ){
    int b = row - hblk*B_SZ;
    src = x + (size_t)b*DIN;
    dst = g_xb + (size_t)row*DIN;
  } else {
    int id = row - NH*B_SZ;
    int om = id % (NOUT*MM);
    src = z + (size_t)om*DIN;
    dst = g_zb + (size_t)id*DIN;
  }
  float4 xv = *(const float4*)(src + col);
  float v0 = xv.x * sscal[col];
  float v1 = xv.y * sscal[col+1];
  float v2 = xv.z * sscal[col+2];
  float v3 = xv.w * sscal[col+3];
  uint2 pk = make_uint2(pack_bf16x2(v0,v1), pack_bf16x2(v2,v3));
  *(uint2*)(dst + col) = pk;

  float p = v0*v0 + v1*v1 + v2*v2 + v3*v3;
  #pragma unroll
  for (int o=16;o;o>>=1) p += __shfl_down_sync(0xffffffffu, p, o);
  if (lane == 0) sw[wid] = p;
  __syncthreads();
  if (tid < 4){
    float t = sw[2*tid] + sw[2*tid+1];
    int r = row0 + tid;
    if (r < NH*B_SZ) g_x2[r] = t; else g_z2[r - NH*B_SZ] = t;
  }
}

// ============ k_main: resident x, G=4, K=64 chunks, 2-stage z ring ============
#define OFF_X2   0        // 512
#define OFF_Z2   512      // 512
#define OFF_XR   3584     // 67584 -> 71168
#define OFF_ZR   71168    // 2*18432 = 36864 -> 108032
// rare-path overlay (clobbers XR/ZR):
#define OFF_RK   3584
#define OFF_RX   38400
#define OFF_RY   73216    // -> 108032
#define SMEM_MAIN 108032

__global__ __launch_bounds__(256,2) void k_main(const float* __restrict__ u_mean,
                                                const float* __restrict__ u_tril,
                                                float* __restrict__ out){
  extern __shared__ char smc[];
  uint32_t sb = smem_u32(smc);
  float* sx2 = (float*)(smc + OFF_X2);
  float* sz2 = (float*)(smc + OFF_Z2);

  int ho0 = blockIdx.y * G;
  int h   = ho0 / NOUT;
  int b0  = blockIdx.x * MM;
  int tid = threadIdx.x;
  int wid = tid >> 5, lane = tid & 31;
  int wr = wid >> 1, wc = wid & 1;
  int l15 = lane & 15, lh = lane >> 4;
  int lane4 = lane >> 2, lpair = (lane & 3)*2;

  if (tid < MM) sx2[tid] = g_x2[h*B_SZ + b0 + tid];

  const __nv_bfloat16* xb = g_xb + ((size_t)h*B_SZ + b0)*DIN;
  float sf2 = g_sf2v[h];

  uint32_t zr_base[2] = { sb + OFF_ZR, sb + OFF_ZR + ZST64 };

  // stage resident x + z chunk 0 (one commit group)
  {
    #pragma unroll
    for (int it=0; it<16; it++){
      int seg = tid + it*256;
      int r = seg >> 5, q = seg & 31;
      CP16(sb + OFF_XR + r*XP + q*16, xb + (size_t)r*DIN + q*8);
    }
    const __nv_bfloat16* zb0 = g_zb + (size_t)ho0*MM*DIN;
    #pragma unroll
    for (int it=0; it<4; it++){
      int seg = tid + it*256;
      int r = seg >> 3, q = seg & 7;
      CP16(zr_base[0] + r*SP64 + q*16, zb0 + (size_t)r*DIN + q*8);
    }
    CP_COMMIT();
  }

  uint32_t aoffA = (wr*32 + l15)*XP + lh*16;
  uint32_t boffA = (wc*64 + l15)*SP64 + lh*16;

  #pragma unroll 1
  for (int g=0; g<G; g++){
    int ho = ho0 + g;
    if (tid < MM) sz2[tid] = g_z2[ho*MM + tid];

    float acc[16][4];
    #pragma unroll
    for (int i=0;i<16;i++)
      #pragma unroll
      for (int j=0;j<4;j++) acc[i][j]=0.f;

    #pragma unroll 1
    for (int c=0;c<4;c++){
      int t = g*4 + c;
      int tn = t + 1;
      if (tn < G*4){
        const __nv_bfloat16* zbn = g_zb + (size_t)(ho0 + (tn>>2))*MM*DIN + (size_t)(tn&3)*64;
        #pragma unroll
        for (int it=0; it<4; it++){
          int seg = tid + it*256;
          int r = seg >> 3, q = seg & 7;
          CP16(zr_base[tn&1] + r*SP64 + q*16, zbn + (size_t)r*DIN + q*8);
        }
      }
      CP_COMMIT();
      CP_WAIT(1);           // chunk t (and x on t=0) arrived
      __syncthreads();
      chunk64x(sb + OFF_XR + aoffA + c*128, zr_base[t&1] + boffA, acc);
    }

    // epilogue: d2 pass + warp exp-skip vote
    float locmin = 1e30f;
    #pragma unroll
    for (int mt=0;mt<2;mt++){
      int r0 = wr*32 + mt*16 + lane4;
      int r1 = r0 + 8;
      float x20 = sx2[r0], x21 = sx2[r1];
      #pragma unroll
      for (int nf=0;nf<8;nf++){
        int cb = wc*64 + nf*8 + lpair;
        float z20 = sz2[cb], z21 = sz2[cb+1];
        float* a4 = acc[mt*8+nf];
        a4[0] = fmaxf(x20 + z20 - 2.f*a4[0], 0.f);
        a4[1] = fmaxf(x20 + z21 - 2.f*a4[1], 0.f);
        a4[2] = fmaxf(x21 + z20 - 2.f*a4[2], 0.f);
        a4[3] = fmaxf(x21 + z21 - 2.f*a4[3], 0.f);
        locmin = fminf(locmin, fminf(fminf(a4[0],a4[1]), fminf(a4[2],a4[3])));
      }
    }
    int allbig = __all_sync(0xffffffffu, locmin >= D2CUT);
    uint32_t nzbits = 0;
    if (!allbig){
      #pragma unroll
      for (int mt=0;mt<2;mt++){
        #pragma unroll
        for (int nf=0;nf<8;nf++){
          float* a4 = acc[mt*8+nf];
          a4[0] = rbf(sf2, a4[0]);
          a4[1] = rbf(sf2, a4[1]);
          a4[2] = rbf(sf2, a4[2]);
          a4[3] = rbf(sf2, a4[3]);
          nzbits |= __float_as_uint(a4[0]) | __float_as_uint(a4[1]) |
                    __float_as_uint(a4[2]) | __float_as_uint(a4[3]);
        }
      }
    }

    int any = __syncthreads_or((int)nzbits);

    if (!any){
      if (tid < MM){
        size_t base = (size_t)ho*B_SZ + b0 + tid;
        out[base] = 0.f;
        out[(size_t)HOC*B_SZ + base] = sf2;
      }
      continue;
    }

    // ================= RARE path (self-sufficient; clobbers XR/ZR) =================
    CP_WAIT(0);
    __syncthreads();
    int o = ho % NOUT;
    float dK = sf2 + JIT;
    float c0 = 1.0f / dK;

    // 1. dump kuf to global scratch, layout [b][m]
    {
      __nv_bfloat16* ksc = g_kscr + (size_t)(blockIdx.y*(B_SZ/MM) + blockIdx.x)*MM*MM;
      #pragma unroll
      for (int mt=0;mt<2;mt++){
        int r0 = wr*32 + mt*16 + lane4;
        int r1 = r0 + 8;
        #pragma unroll
        for (int nf=0;nf<8;nf++){
          int cb = wc*64 + nf*8 + lpair;
          float* a4 = acc[mt*8+nf];
          uint32_t w0, w1;
          if (allbig){ w0 = 0u; w1 = 0u; }
          else { w0 = pack_bf16x2(a4[0],a4[1]); w1 = pack_bf16x2(a4[2],a4[3]); }
          *(uint32_t*)&ksc[(size_t)r0*MM + cb] = w0;
          *(uint32_t*)&ksc[(size_t)r1*MM + cb] = w1;
        }
      }
    }

    // 2. build Kuu bf16 (scalar), Xb = c0*I
    {
      const __nv_bfloat16* zrows = g_zb + (size_t)ho*MM*DIN;
      for (int idx = tid; idx < MM*MM; idx += 256){
        int i = idx >> 7, j = idx & 127;
        float dot = 0.f;
        const __nv_bfloat16* zi = zrows + (size_t)i*DIN;
        const __nv_bfloat16* zj = zrows + (size_t)j*DIN;
        for (int d=0; d<DIN; d++)
          dot += __bfloat162float(zi[d]) * __bfloat162float(zj[d]);
        float d2 = fmaxf(g_z2[ho*MM+i] + g_z2[ho*MM+j] - 2.f*dot, 0.f);
        float kv = (i==j) ? dK : rbf(sf2, d2);
        ((__nv_bfloat16*)(smc + OFF_RK + i*KPITCH))[j] = __float2bfloat16(kv);
        ((__nv_bfloat16*)(smc + OFF_RX + i*KPITCH))[j] = __float2bfloat16((i==j) ? c0 : 0.f);
      }
    }
    __syncthreads();

    // 3. Newton-Schulz x2 (tensor)
    #pragma unroll 1
    for (int it=0; it<2; it++){
      {
        float a2[16][4];
        #pragma unroll
        for (int i=0;i<16;i++)
          #pragma unroll
          for (int j=0;j<4;j++) a2[i][j]=0.f;
        mm128(sb + OFF_RK, sb + OFF_RX, wr, wc, l15, lh, a2);
        #pragma unroll
        for (int mt=0;mt<2;mt++){
          int r0 = wr*32 + mt*16 + lane4;
          int r1 = r0 + 8;
          #pragma unroll
          for (int nf=0;nf<8;nf++){
            int cb = wc*64 + nf*8 + lpair;
            float* a4 = a2[mt*8+nf];
            *(uint32_t*)(smc + OFF_RY + r0*KPITCH + cb*2) = pack_bf16x2(a4[0],a4[1]);
            *(uint32_t*)(smc + OFF_RY + r1*KPITCH + cb*2) = pack_bf16x2(a4[2],a4[3]);
          }
        }
      }
      __syncthreads();
      {
        float a2[16][4];
        #pragma unroll
        for (int i=0;i<16;i++)
          #pragma unroll
          for (int j=0;j<4;j++) a2[i][j]=0.f;
        mm128(sb + OFF_RX, sb + OFF_RY, wr, wc, l15, lh, a2);
        __syncthreads();
        #pragma unroll
        for (int mt=0;mt<2;mt++){
          int r0 = wr*32 + mt*16 + lane4;
          int r1 = r0 + 8;
          #pragma unroll
          for (int nf=0;nf<8;nf++){
            int cb = wc*64 + nf*8 + lpair;
            uint32_t p0 = *(const uint32_t*)(smc + OFF_RX + r0*KPITCH + cb*2);
            uint32_t p1 = *(const uint32_t*)(smc + OFF_RX + r1*KPITCH + cb*2);
            __nv_bfloat162 h0 = *reinterpret_cast<__nv_bfloat162*>(&p0);
            __nv_bfloat162 h1 = *reinterpret_cast<__nv_bfloat162*>(&p1);
            float* a4 = a2[mt*8+nf];
            *(uint32_t*)(smc + OFF_RX + r0*KPITCH + cb*2) =
              pack_bf16x2(2.f*__low2float(h0)-a4[0], 2.f*__high2float(h0)-a4[1]);
            *(uint32_t*)(smc + OFF_RX + r1*KPITCH + cb*2) =
              pack_bf16x2(2.f*__low2float(h1)-a4[2], 2.f*__high2float(h1)-a4[3]);
          }
        }
      }
      __syncthreads();
    }

    // 4. scalar apply per column b
    if (tid < MM){
      const __nv_bfloat16* ksc = g_kscr + (size_t)(blockIdx.y*(B_SZ/MM) + blockIdx.x)*MM*MM
                               + (size_t)tid*MM;
      const float* Lv = u_tril + (size_t)o*TRILN;
      const float* um = u_mean + o*MM;
      float w[MM];
      for (int m=0;m<MM;m++){
        const __nv_bfloat16* prow = (const __nv_bfloat16*)(smc + OFF_RX + m*KPITCH);
        float s = 0.f;
        for (int k=0;k<MM;k++) s += __bfloat162float(prow[k]) * __bfloat162float(ksc[k]);
        w[m] = s;
      }
      float diag1 = 0.f, mu = 0.f;
      for (int m=0;m<MM;m++){
        diag1 += w[m]*__bfloat162float(ksc[m]);
        mu    += w[m]*um[m];
      }
      float diag2 = 0.f;
      for (int j=0;j<MM;j++){
        float u = 0.f;
        for (int k=j;k<MM;k++) u += Lv[(k*(k+1))/2 + j] * w[k];
        diag2 += u*u;
      }
      size_t base = (size_t)ho*B_SZ + b0 + tid;
      out[base] = mu;
      out[(size_t)HOC*B_SZ + base] = sf2 - diag1 + diag2;
    }
    __syncthreads();

    // 5. restore resident x + z chunk for next group (matches mainloop pattern)
    if (g+1 < G){
      if (tid < MM) sx2[tid] = g_x2[h*B_SZ + b0 + tid];
      #pragma unroll
      for (int it=0; it<16; it++){
        int seg = tid + it*256;
        int rr = seg >> 5, q = seg & 31;
        CP16(sb + OFF_XR + rr*XP + q*16, xb + (size_t)rr*DIN + q*8);
      }
      int t0 = (g+1)*4;
      const __nv_bfloat16* zbn = g_zb + (size_t)(ho0+g+1)*MM*DIN;
      #pragma unroll
      for (int it=0; it<4; it++){
        int seg = tid + it*256;
        int r = seg >> 3, q = seg & 7;
        CP16(zr_base[t0&1] + r*SP64 + q*16, zbn + (size_t)r*DIN + q*8);
      }
      CP_COMMIT();   // x + chunk t0 as one group; next iter's commit+wait(1) drains it
    }
  }
}

// ---------------- launch ----------------
extern "C" void kernel_launch(void* const* d_in, const int* in_sizes, int n_in,
                              void* d_out, int out_size){
  const float* x      = (const float*)d_in[0];
  const float* z      = (const float*)d_in[1];
  const float* u_mean = (const float*)d_in[2];
  const float* u_tril = (const float*)d_in[3];
  const float* theta  = (const float*)d_in[4];
  float* out = (float*)d_out;

  cudaFuncSetAttribute(k_main, cudaFuncAttributeMaxDynamicSharedMemorySize, SMEM_MAIN);

  k_prep<<<(NH*B_SZ + HOC*MM)/4, 256>>>(x, z, theta);
  k_main<<<dim3(B_SZ/MM, HOC/G), 256, SMEM_MAIN>>>(u_mean, u_tril, out);
}

// round 17
// speedup vs baseline: 1.0411x; 1.0411x over previous
#include <cuda_runtime.h>
#include <cuda_bf16.h>
#include <math.h>
#include <cstdint>

#define B_SZ  4096
#define DIN   256
#define NOUT  32
#define MM    128
#define NH    2
#define HOC   (NH*NOUT)
#define JIT   1e-4f
#define TRILN (MM*(MM+1)/2)
#define D2CUT 170.0f

// ---------------- scratch ----------------
__device__ float g_sf2v[NH];
__device__ float g_x2[NH*B_SZ];
__device__ float g_z2[HOC*MM];
__device__ __align__(16) __nv_bfloat16 g_xb[NH*B_SZ*DIN];
__device__ __align__(16) __nv_bfloat16 g_zb[HOC*MM*DIN];
__device__ __align__(16) __nv_bfloat16 g_kscr[1024*MM*MM];  // rare-path kuf scratch

// ---------------- helpers ----------------
__device__ __forceinline__ uint32_t smem_u32(const void* p){
  uint32_t a;
  asm("{ .reg .u64 t; cvta.to.shared.u64 t, %1; cvt.u32.u64 %0, t; }" : "=r"(a) : "l"(p));
  return a;
}
__device__ __forceinline__ void ldsm4(uint32_t addr, uint32_t* r){
  asm volatile("ldmatrix.sync.aligned.m8n8.x4.shared.b16 {%0,%1,%2,%3}, [%4];"
    : "=r"(r[0]),"=r"(r[1]),"=r"(r[2]),"=r"(r[3]) : "r"(addr));
}
__device__ __forceinline__ void mma16816(float* c, const uint32_t* a, const uint32_t* b){
  asm volatile("mma.sync.aligned.m16n8k16.row.col.f32.bf16.bf16.f32 "
    "{%0,%1,%2,%3}, {%4,%5,%6,%7}, {%8,%9}, {%0,%1,%2,%3};"
    : "+f"(c[0]),"+f"(c[1]),"+f"(c[2]),"+f"(c[3])
    : "r"(a[0]),"r"(a[1]),"r"(a[2]),"r"(a[3]), "r"(b[0]),"r"(b[1]));
}
#define CP16(dst, src) asm volatile("cp.async.cg.shared.global [%0], [%1], 16;" :: "r"(dst), "l"(src))
#define CP_COMMIT()    asm volatile("cp.async.commit_group;" ::: "memory")
#define CP_WAIT(n)     asm volatile("cp.async.wait_group %0;" :: "n"(n) : "memory")

__device__ __forceinline__ uint32_t pack_bf16x2(float lo, float hi){
  uint32_t r;
  asm("cvt.rn.satfinite.bf16x2.f32 %0, %1, %2;" : "=r"(r) : "f"(hi), "f"(lo));
  return r;
}
__device__ __forceinline__ float rbf(float sf2, float d2){
  return (d2 < D2CUT) ? sf2*__expf(-0.5f*d2) : 0.f;
}

#define SP64   144      // K=64 stage pitch bytes
#define ZST64  18432    // one K=64 z stage
#define KPITCH 272
#define XP     528
#define G      2

// 128x128x128 bf16 block GEMM from KPITCH tiles (rare-path NS)
__device__ __forceinline__ void mm128(uint32_t aBase, uint32_t bBase,
                                      int wr, int wc, int l15, int lh,
                                      float acc[16][4]){
  uint32_t aB0 = aBase + (wr*32 + l15)*KPITCH + lh*16;
  uint32_t bB0 = bBase + (wc*64 + l15)*KPITCH + lh*16;
  #pragma unroll
  for (int ks=0;ks<8;ks++){
    uint32_t af[2][4], bt[4], bfr[8][2];
    #pragma unroll
    for (int mt=0;mt<2;mt++) ldsm4(aB0 + ks*32 + mt*16*KPITCH, af[mt]);
    #pragma unroll
    for (int nn=0;nn<4;nn++){
      ldsm4(bB0 + ks*32 + nn*16*KPITCH, bt);
      bfr[nn*2][0]=bt[0]; bfr[nn*2][1]=bt[2];
      bfr[nn*2+1][0]=bt[1]; bfr[nn*2+1][1]=bt[3];
    }
    #pragma unroll
    for (int mt=0;mt<2;mt++)
      #pragma unroll
      for (int nf=0;nf<8;nf++)
        mma16816(acc[mt*8+nf], af[mt], bfr[nf]);
  }
}

// one K=64 chunk: A resident x (XP pitch), B z stage (SP64 pitch)
__device__ __forceinline__ void chunk64x(uint32_t aB, uint32_t bB, float acc[16][4]){
  #pragma unroll
  for (int ks=0;ks<4;ks++){
    uint32_t af[2][4], bt[4], bfr[8][2];
    #pragma unroll
    for (int mt=0;mt<2;mt++) ldsm4(aB + ks*32 + mt*16*XP, af[mt]);
    #pragma unroll
    for (int nn=0;nn<4;nn++){
      ldsm4(bB + ks*32 + nn*16*SP64, bt);
      bfr[nn*2][0]=bt[0]; bfr[nn*2][1]=bt[2];
      bfr[nn*2+1][0]=bt[1]; bfr[nn*2+1][1]=bt[3];
    }
    #pragma unroll
    for (int mt=0;mt<2;mt++)
      #pragma unroll
      for (int nf=0;nf<8;nf++)
        mma16816(acc[mt*8+nf], af[mt], bfr[nf]);
  }
}

// ---------------- prep: 8 rows/block, 8 elems/thread ----------------
__global__ void k_prep(const float* __restrict__ x, const float* __restrict__ z,
                       const float* __restrict__ theta){
  __shared__ float sscal[256];
  __shared__ float sw[8];
  int tid = threadIdx.x;
  int lane = tid & 31, wid = tid >> 5;
  int row0 = blockIdx.x*8;
  int hblk = (row0 < NH*B_SZ) ? (row0 / B_SZ)
                              : ((row0 - NH*B_SZ) / (NOUT*MM));
  sscal[tid] = expf(-theta[hblk*(DIN+1) + 1 + tid]);
  if (blockIdx.x == 0 && tid < NH) g_sf2v[tid] = expf(theta[tid*(DIN+1)]);
  __syncthreads();

  int rloc = tid >> 5;            // 8 rows, one warp each
  int col  = (tid & 31) << 3;     // 8 elems per thread
  int row  = row0 + rloc;

  const float* src; __nv_bfloat16* dst;
  if (row < NH*B_SZ){
    int b = row - hblk*B_SZ;
    src = x + (size_t)b*DIN;
    dst = g_xb + (size_t)row*DIN;
  } else {
    int id = row - NH*B_SZ;
    int om = id % (NOUT*MM);
    src = z + (size_t)om*DIN;
    dst = g_zb + (size_t)id*DIN;
  }
  float4 xv0 = *(const float4*)(src + col);
  float4 xv1 = *(const float4*)(src + col + 4);
  float v0 = xv0.x * sscal[col];
  float v1 = xv0.y * sscal[col+1];
  float v2 = xv0.z * sscal[col+2];
  float v3 = xv0.w * sscal[col+3];
  float v4 = xv1.x * sscal[col+4];
  float v5 = xv1.y * sscal[col+5];
  float v6 = xv1.z * sscal[col+6];
  float v7 = xv1.w * sscal[col+7];
  uint4 pk;
  pk.x = pack_bf16x2(v0,v1); pk.y = pack_bf16x2(v2,v3);
  pk.z = pack_bf16x2(v4,v5); pk.w = pack_bf16x2(v6,v7);
  *(uint4*)(dst + col) = pk;

  float p = v0*v0+v1*v1+v2*v2+v3*v3+v4*v4+v5*v5+v6*v6+v7*v7;
  #pragma unroll
  for (int o=16;o;o>>=1) p += __shfl_down_sync(0xffffffffu, p, o);
  if (lane == 0) sw[wid] = p;
  __syncthreads();
  if (tid < 8){
    float t = sw[tid];
    int r = row0 + tid;
    if (r < NH*B_SZ) g_x2[r] = t; else g_z2[r - NH*B_SZ] = t;
  }
}

// ============ k_main: resident x, G=2, K=64 chunks, 2-stage z ring (race-free) ============
#define OFF_X2   0
#define OFF_Z2   512
#define OFF_XR   3584     // 67584 -> 71168
#define OFF_ZR   71168    // 2*18432 -> 108032
// rare-path overlay:
#define OFF_RK   3584
#define OFF_RX   38400
#define OFF_RY   73216
#define SMEM_MAIN 108032

__global__ __launch_bounds__(256,2) void k_main(const float* __restrict__ u_mean,
                                                const float* __restrict__ u_tril,
                                                float* __restrict__ out){
  extern __shared__ char smc[];
  uint32_t sb = smem_u32(smc);
  float* sx2 = (float*)(smc + OFF_X2);
  float* sz2 = (float*)(smc + OFF_Z2);

  int ho0 = blockIdx.y * G;
  int h   = ho0 / NOUT;
  int b0  = blockIdx.x * MM;
  int tid = threadIdx.x;
  int wid = tid >> 5, lane = tid & 31;
  int wr = wid >> 1, wc = wid & 1;
  int l15 = lane & 15, lh = lane >> 4;
  int lane4 = lane >> 2, lpair = (lane & 3)*2;

  if (tid < MM) sx2[tid] = g_x2[h*B_SZ + b0 + tid];

  const __nv_bfloat16* xb = g_xb + ((size_t)h*B_SZ + b0)*DIN;
  float sf2 = g_sf2v[h];

  uint32_t zr_base[2] = { sb + OFF_ZR, sb + OFF_ZR + ZST64 };

  // stage resident x + z chunk 0 (one commit group)
  {
    #pragma unroll
    for (int it=0; it<16; it++){
      int seg = tid + it*256;
      int r = seg >> 5, q = seg & 31;
      CP16(sb + OFF_XR + r*XP + q*16, xb + (size_t)r*DIN + q*8);
    }
    const __nv_bfloat16* zb0 = g_zb + (size_t)ho0*MM*DIN;
    #pragma unroll
    for (int it=0; it<4; it++){
      int seg = tid + it*256;
      int r = seg >> 3, q = seg & 7;
      CP16(zr_base[0] + r*SP64 + q*16, zb0 + (size_t)r*DIN + q*8);
    }
    CP_COMMIT();
  }

  uint32_t aoffA = (wr*32 + l15)*XP + lh*16;
  uint32_t boffA = (wc*64 + l15)*SP64 + lh*16;

  #pragma unroll 1
  for (int g=0; g<G; g++){
    int ho = ho0 + g;
    if (tid < MM) sz2[tid] = g_z2[ho*MM + tid];

    float acc[16][4];
    #pragma unroll
    for (int i=0;i<16;i++)
      #pragma unroll
      for (int j=0;j<4;j++) acc[i][j]=0.f;

    #pragma unroll 1
    for (int c=0;c<4;c++){
      int t = g*4 + c;
      CP_WAIT(0);           // chunk t (and x on t=0) fully arrived
      __syncthreads();      // all warps done with stage (t-1) compute
      int tn = t + 1;
      if (tn < G*4){        // prefetch t+1 into the now-free stage (race-free)
        const __nv_bfloat16* zbn = g_zb + (size_t)(ho0 + (tn>>2))*MM*DIN + (size_t)(tn&3)*64;
        #pragma unroll
        for (int it=0; it<4; it++){
          int seg = tid + it*256;
          int r = seg >> 3, q = seg & 7;
          CP16(zr_base[tn&1] + r*SP64 + q*16, zbn + (size_t)r*DIN + q*8);
        }
        CP_COMMIT();
      }
      chunk64x(sb + OFF_XR + aoffA + c*128, zr_base[t&1] + boffA, acc);
    }

    // epilogue: d2 pass + warp exp-skip vote
    float locmin = 1e30f;
    #pragma unroll
    for (int mt=0;mt<2;mt++){
      int r0 = wr*32 + mt*16 + lane4;
      int r1 = r0 + 8;
      float x20 = sx2[r0], x21 = sx2[r1];
      #pragma unroll
      for (int nf=0;nf<8;nf++){
        int cb = wc*64 + nf*8 + lpair;
        float z20 = sz2[cb], z21 = sz2[cb+1];
        float* a4 = acc[mt*8+nf];
        a4[0] = fmaxf(x20 + z20 - 2.f*a4[0], 0.f);
        a4[1] = fmaxf(x20 + z21 - 2.f*a4[1], 0.f);
        a4[2] = fmaxf(x21 + z20 - 2.f*a4[2], 0.f);
        a4[3] = fmaxf(x21 + z21 - 2.f*a4[3], 0.f);
        locmin = fminf(locmin, fminf(fminf(a4[0],a4[1]), fminf(a4[2],a4[3])));
      }
    }
    int allbig = __all_sync(0xffffffffu, locmin >= D2CUT);
    uint32_t nzbits = 0;
    if (!allbig){
      #pragma unroll
      for (int mt=0;mt<2;mt++){
        #pragma unroll
        for (int nf=0;nf<8;nf++){
          float* a4 = acc[mt*8+nf];
          a4[0] = rbf(sf2, a4[0]);
          a4[1] = rbf(sf2, a4[1]);
          a4[2] = rbf(sf2, a4[2]);
          a4[3] = rbf(sf2, a4[3]);
          nzbits |= __float_as_uint(a4[0]) | __float_as_uint(a4[1]) |
                    __float_as_uint(a4[2]) | __float_as_uint(a4[3]);
        }
      }
    }

    int any = __syncthreads_or((int)nzbits);

    if (!any){
      if (tid < MM){
        size_t base = (size_t)ho*B_SZ + b0 + tid;
        out[base] = 0.f;
        out[(size_t)HOC*B_SZ + base] = sf2;
      }
      continue;
    }

    // ================= RARE path (self-sufficient; clobbers XR/ZR) =================
    CP_WAIT(0);
    __syncthreads();
    int o = ho % NOUT;
    float dK = sf2 + JIT;
    float c0 = 1.0f / dK;

    {
      __nv_bfloat16* ksc = g_kscr + (size_t)(blockIdx.y*(B_SZ/MM) + blockIdx.x)*MM*MM;
      #pragma unroll
      for (int mt=0;mt<2;mt++){
        int r0 = wr*32 + mt*16 + lane4;
        int r1 = r0 + 8;
        #pragma unroll
        for (int nf=0;nf<8;nf++){
          int cb = wc*64 + nf*8 + lpair;
          float* a4 = acc[mt*8+nf];
          uint32_t w0, w1;
          if (allbig){ w0 = 0u; w1 = 0u; }
          else { w0 = pack_bf16x2(a4[0],a4[1]); w1 = pack_bf16x2(a4[2],a4[3]); }
          *(uint32_t*)&ksc[(size_t)r0*MM + cb] = w0;
          *(uint32_t*)&ksc[(size_t)r1*MM + cb] = w1;
        }
      }
    }

    {
      const __nv_bfloat16* zrows = g_zb + (size_t)ho*MM*DIN;
      for (int idx = tid; idx < MM*MM; idx += 256){
        int i = idx >> 7, j = idx & 127;
        float dot = 0.f;
        const __nv_bfloat16* zi = zrows + (size_t)i*DIN;
        const __nv_bfloat16* zj = zrows + (size_t)j*DIN;
        for (int d=0; d<DIN; d++)
          dot += __bfloat162float(zi[d]) * __bfloat162float(zj[d]);
        float d2 = fmaxf(g_z2[ho*MM+i] + g_z2[ho*MM+j] - 2.f*dot, 0.f);
        float kv = (i==j) ? dK : rbf(sf2, d2);
        ((__nv_bfloat16*)(smc + OFF_RK + i*KPITCH))[j] = __float2bfloat16(kv);
        ((__nv_bfloat16*)(smc + OFF_RX + i*KPITCH))[j] = __float2bfloat16((i==j) ? c0 : 0.f);
      }
    }
    __syncthreads();

    #pragma unroll 1
    for (int it=0; it<2; it++){
      {
        float a2[16][4];
        #pragma unroll
        for (int i=0;i<16;i++)
          #pragma unroll
          for (int j=0;j<4;j++) a2[i][j]=0.f;
        mm128(sb + OFF_RK, sb + OFF_RX, wr, wc, l15, lh, a2);
        #pragma unroll
        for (int mt=0;mt<2;mt++){
          int r0 = wr*32 + mt*16 + lane4;
          int r1 = r0 + 8;
          #pragma unroll
          for (int nf=0;nf<8;nf++){
            int cb = wc*64 + nf*8 + lpair;
            float* a4 = a2[mt*8+nf];
            *(uint32_t*)(smc + OFF_RY + r0*KPITCH + cb*2) = pack_bf16x2(a4[0],a4[1]);
            *(uint32_t*)(smc + OFF_RY + r1*KPITCH + cb*2) = pack_bf16x2(a4[2],a4[3]);
          }
        }
      }
      __syncthreads();
      {
        float a2[16][4];
        #pragma unroll
        for (int i=0;i<16;i++)
          #pragma unroll
          for (int j=0;j<4;j++) a2[i][j]=0.f;
        mm128(sb + OFF_RX, sb + OFF_RY, wr, wc, l15, lh, a2);
        __syncthreads();
        #pragma unroll
        for (int mt=0;mt<2;mt++){
          int r0 = wr*32 + mt*16 + lane4;
          int r1 = r0 + 8;
          #pragma unroll
          for (int nf=0;nf<8;nf++){
            int cb = wc*64 + nf*8 + lpair;
            uint32_t p0 = *(const uint32_t*)(smc + OFF_RX + r0*KPITCH + cb*2);
            uint32_t p1 = *(const uint32_t*)(smc + OFF_RX + r1*KPITCH + cb*2);
            __nv_bfloat162 h0 = *reinterpret_cast<__nv_bfloat162*>(&p0);
            __nv_bfloat162 h1 = *reinterpret_cast<__nv_bfloat162*>(&p1);
            float* a4 = a2[mt*8+nf];
            *(uint32_t*)(smc + OFF_RX + r0*KPITCH + cb*2) =
              pack_bf16x2(2.f*__low2float(h0)-a4[0], 2.f*__high2float(h0)-a4[1]);
            *(uint32_t*)(smc + OFF_RX + r1*KPITCH + cb*2) =
              pack_bf16x2(2.f*__low2float(h1)-a4[2], 2.f*__high2float(h1)-a4[3]);
          }
        }
      }
      __syncthreads();
    }

    if (tid < MM){
      const __nv_bfloat16* ksc = g_kscr + (size_t)(blockIdx.y*(B_SZ/MM) + blockIdx.x)*MM*MM
                               + (size_t)tid*MM;
      const float* Lv = u_tril + (size_t)o*TRILN;
      const float* um = u_mean + o*MM;
      float w[MM];
      for (int m=0;m<MM;m++){
        const __nv_bfloat16* prow = (const __nv_bfloat16*)(smc + OFF_RX + m*KPITCH);
        float s = 0.f;
        for (int k=0;k<MM;k++) s += __bfloat162float(prow[k]) * __bfloat162float(ksc[k]);
        w[m] = s;
      }
      float diag1 = 0.f, mu = 0.f;
      for (int m=0;m<MM;m++){
        diag1 += w[m]*__bfloat162float(ksc[m]);
        mu    += w[m]*um[m];
      }
      float diag2 = 0.f;
      for (int j=0;j<MM;j++){
        float u = 0.f;
        for (int k=j;k<MM;k++) u += Lv[(k*(k+1))/2 + j] * w[k];
        diag2 += u*u;
      }
      size_t base = (size_t)ho*B_SZ + b0 + tid;
      out[base] = mu;
      out[(size_t)HOC*B_SZ + base] = sf2 - diag1 + diag2;
    }
    __syncthreads();

    if (g+1 < G){
      if (tid < MM) sx2[tid] = g_x2[h*B_SZ + b0 + tid];
      #pragma unroll
      for (int it=0; it<16; it++){
        int seg = tid + it*256;
        int rr = seg >> 5, q = seg & 31;
        CP16(sb + OFF_XR + rr*XP + q*16, xb + (size_t)rr*DIN + q*8);
      }
      int t0 = (g+1)*4;
      const __nv_bfloat16* zbn = g_zb + (size_t)(ho0+g+1)*MM*DIN;
      #pragma unroll
      for (int it=0; it<4; it++){
        int seg = tid + it*256;
        int r = seg >> 3, q = seg & 7;
        CP16(zr_base[t0&1] + r*SP64 + q*16, zbn + (size_t)r*DIN + q*8);
      }
      CP_COMMIT();
    }
  }
}

// ---------------- launch ----------------
extern "C" void kernel_launch(void* const* d_in, const int* in_sizes, int n_in,
                              void* d_out, int out_size){
  const float* x      = (const float*)d_in[0];
  const float* z      = (const float*)d_in[1];
  const float* u_mean = (const float*)d_in[2];
  const float* u_tril = (const float*)d_in[3];
  const float* theta  = (const float*)d_in[4];
  float* out = (float*)d_out;

  cudaFuncSetAttribute(k_main, cudaFuncAttributeMaxDynamicSharedMemorySize, SMEM_MAIN);

  k_prep<<<(NH*B_SZ + HOC*MM)/8, 256>>>(x, z, theta);
  k_main<<<dim3(B_SZ/MM, HOC/G), 256, SMEM_MAIN>>>(u_mean, u_tril, out);
}